// round 2
// baseline (speedup 1.0000x reference)
#include <cuda_runtime.h>

#define NN 50001          // N_NODES = ITEM_NUM + 1
#define NE 800000         // N_EDGES
#define EMB 128
#define N4  (NN * 32)     // float4 count per [NN,128] buffer

// ---- scratch (no allocations allowed) ----
__device__ float g_dinv[NN];
__device__ float g_norm[NE];
__device__ float g_h   [NN * EMB];
__device__ float g_bufA[NN * EMB];
__device__ float g_bufB[NN * EMB];

// ---------------------------------------------------------------- utility
__global__ void k_fill1(float* d, int n) {
    int i = blockIdx.x * blockDim.x + threadIdx.x;
    if (i < n) d[i] = 1.0f;   // self-loop contributes 1 to every degree
}

__global__ void k_count(const int* __restrict__ col, float* deg, int e) {
    int i = blockIdx.x * blockDim.x + threadIdx.x;
    if (i < e) atomicAdd(&deg[col[i]], 1.0f);
}

__global__ void k_rsqrt(float* d, int n) {
    int i = blockIdx.x * blockDim.x + threadIdx.x;
    if (i < n) d[i] = rsqrtf(d[i]);   // deg >= 1 always (self-loops)
}

__global__ void k_edge_norm(const int* __restrict__ row, const int* __restrict__ col,
                            const float* __restrict__ dinv, float* __restrict__ nrm, int e) {
    int i = blockIdx.x * blockDim.x + threadIdx.x;
    if (i < e) nrm[i] = dinv[row[i]] * dinv[col[i]];
}

// cur = emb[:NN]; out = emb[:NN]   (out accumulates sum of layer embeddings)
__global__ void k_copy2(const float4* __restrict__ src, float4* __restrict__ cur,
                        float4* __restrict__ out, int n4) {
    int i = blockIdx.x * blockDim.x + threadIdx.x;
    if (i < n4) { float4 v = src[i]; cur[i] = v; out[i] = v; }
}

// agg = h * dinv^2 (self-loop term) + bias
__global__ void k_selfbias(const float4* __restrict__ h, const float* __restrict__ dinv,
                           const float4* __restrict__ b, float4* __restrict__ agg, int n4) {
    int i = blockIdx.x * blockDim.x + threadIdx.x;
    if (i >= n4) return;
    int node = i >> 5;            // 32 float4 per row
    float di = dinv[node];
    float s  = di * di;
    float4 v  = h[i];
    float4 bv = b[i & 31];
    v.x = v.x * s + bv.x;
    v.y = v.y * s + bv.y;
    v.z = v.z * s + bv.z;
    v.w = v.w * s + bv.w;
    agg[i] = v;
}

// out += agg
__global__ void k_add(const float4* __restrict__ a, float4* __restrict__ out, int n4) {
    int i = blockIdx.x * blockDim.x + threadIdx.x;
    if (i >= n4) return;
    float4 o = out[i], v = a[i];
    o.x += v.x; o.y += v.y; o.z += v.z; o.w += v.w;
    out[i] = o;
}

// -------------------------------------------------------- edge scatter
// One warp per edge: lane l owns 4 floats (float4).  agg[col] += h[row]*norm
__global__ void __launch_bounds__(256)
k_scatter(const int* __restrict__ row, const int* __restrict__ col,
          const float* __restrict__ nrm, const float* __restrict__ h,
          float* __restrict__ agg, int e) {
    int w = (blockIdx.x * 256 + threadIdx.x) >> 5;
    if (w >= e) return;
    int lane = threadIdx.x & 31;
    int r = __ldg(row + w);
    int c = __ldg(col + w);
    float s = __ldg(nrm + w);
    float4 v = ((const float4*)h)[r * 32 + lane];
    float* dst = agg + c * EMB + lane * 4;
    asm volatile("red.global.add.v4.f32 [%0], {%1, %2, %3, %4};"
                 :: "l"(dst), "f"(v.x * s), "f"(v.y * s), "f"(v.z * s), "f"(v.w * s)
                 : "memory");
}

// -------------------------------------------------------------- GEMM
// h[row, :] = x[row, :] @ W  (128x128).  W staged in 64KB dynamic smem.
// Warp per row, 8 rows per warp, 64 rows per 256-thread block.
__global__ void __launch_bounds__(256)
k_gemm(const float* __restrict__ x, const float* __restrict__ W,
       float* __restrict__ h, int n) {
    extern __shared__ float4 ws4[];          // 4096 float4 = 64KB: W[k][4l..4l+3]
    const float4* W4 = (const float4*)W;
    int tid = threadIdx.x;
    #pragma unroll
    for (int i = 0; i < 16; i++) ws4[i * 256 + tid] = W4[i * 256 + tid];
    __syncthreads();

    int warp = tid >> 5, lane = tid & 31;
    int rowbase = blockIdx.x * 64 + warp * 8;
    for (int r = 0; r < 8; r++) {
        int row = rowbase + r;
        if (row >= n) break;
        float4 xf = ((const float4*)x)[row * 32 + lane];   // x[row][4l..4l+3]
        float4 acc = make_float4(0.f, 0.f, 0.f, 0.f);
        #pragma unroll 8
        for (int k4 = 0; k4 < 32; k4++) {
            float x0 = __shfl_sync(0xffffffffu, xf.x, k4);   // x[row][4*k4+0]
            float x1 = __shfl_sync(0xffffffffu, xf.y, k4);
            float x2 = __shfl_sync(0xffffffffu, xf.z, k4);
            float x3 = __shfl_sync(0xffffffffu, xf.w, k4);
            float4 w0 = ws4[(k4 * 4 + 0) * 32 + lane];
            acc.x += x0 * w0.x; acc.y += x0 * w0.y; acc.z += x0 * w0.z; acc.w += x0 * w0.w;
            float4 w1 = ws4[(k4 * 4 + 1) * 32 + lane];
            acc.x += x1 * w1.x; acc.y += x1 * w1.y; acc.z += x1 * w1.z; acc.w += x1 * w1.w;
            float4 w2 = ws4[(k4 * 4 + 2) * 32 + lane];
            acc.x += x2 * w2.x; acc.y += x2 * w2.y; acc.z += x2 * w2.z; acc.w += x2 * w2.w;
            float4 w3 = ws4[(k4 * 4 + 3) * 32 + lane];
            acc.x += x3 * w3.x; acc.y += x3 * w3.y; acc.z += x3 * w3.z; acc.w += x3 * w3.w;
        }
        ((float4*)h)[row * 32 + lane] = acc;
    }
}

// ================================================================ launch
extern "C" void kernel_launch(void* const* d_in, const int* in_sizes, int n_in,
                              void* d_out, int out_size) {
    const int*   edge = (const int*)d_in[0];      // [2, NE] int32
    const float* emb  = (const float*)d_in[1];    // [100001, 128] f32
    const float* W    = (const float*)d_in[2];    // [3, 128, 128]
    const float* b    = (const float*)d_in[3];    // [3, 128]
    float* out = (float*)d_out;                   // [NN, 128]

    const int* row = edge;
    const int* col = edge + NE;

    float *dinv, *nrm, *h, *bufA, *bufB;
    cudaGetSymbolAddress((void**)&dinv, g_dinv);
    cudaGetSymbolAddress((void**)&nrm,  g_norm);
    cudaGetSymbolAddress((void**)&h,    g_h);
    cudaGetSymbolAddress((void**)&bufA, g_bufA);
    cudaGetSymbolAddress((void**)&bufB, g_bufB);

    cudaFuncSetAttribute(k_gemm, cudaFuncAttributeMaxDynamicSharedMemorySize, 65536);

    const int gN  = (NN + 255) / 256;
    const int gE  = (NE + 255) / 256;
    const int g4  = (N4 + 255) / 256;
    const int gSc = (NE * 32) / 256;              // warp per edge
    const int gG  = (NN + 63) / 64;

    // degrees / norms (shared by all layers)
    k_fill1   <<<gN, 256>>>(dinv, NN);
    k_count   <<<gE, 256>>>(col, dinv, NE);
    k_rsqrt   <<<gN, 256>>>(dinv, NN);
    k_edge_norm<<<gE, 256>>>(row, col, dinv, nrm, NE);

    // out = cur = item_emb[:NN]
    k_copy2<<<g4, 256>>>((const float4*)emb, (float4*)bufA, (float4*)out, N4);

    float* cur = bufA;
    float* nxt = bufB;
    for (int l = 0; l < 3; l++) {
        k_gemm    <<<gG, 256, 65536>>>(cur, W + l * EMB * EMB, h, NN);
        k_selfbias<<<g4, 256>>>((const float4*)h, dinv, (const float4*)(b + l * EMB),
                                (float4*)nxt, N4);
        k_scatter <<<gSc, 256>>>(row, col, nrm, h, nxt, NE);
        k_add     <<<g4, 256>>>((const float4*)nxt, (float4*)out, N4);
        float* t = cur; cur = nxt; nxt = t;
    }
}

// round 3
// speedup vs baseline: 1.2228x; 1.2228x over previous
#include <cuda_runtime.h>

#define NN 50001          // N_NODES
#define NE 800000
#define EMB 128
#define N4  (NN * 32)     // float4 per [NN,128]

// ---- scratch (device globals; no allocations allowed) ----
__device__ float g_dinv[NN];
__device__ int   g_cnt [NN];
__device__ int   g_off [NN + 1];
__device__ int   g_cur [NN];
__device__ int2  g_edge[NE];      // (src, __float_as_int(dinv[src]))
__device__ float g_h   [NN * EMB];
__device__ float g_bufA[NN * EMB];
__device__ float g_bufB[NN * EMB];

// ---------------------------------------------------------------- prologue
__global__ void k_zero(int* c, int n) {
    int i = blockIdx.x * blockDim.x + threadIdx.x;
    if (i < n) c[i] = 0;
}

__global__ void k_cnt(const int* __restrict__ col, int* cnt, int e) {
    int i = blockIdx.x * blockDim.x + threadIdx.x;
    if (i < e) atomicAdd(&cnt[col[i]], 1);
}

__global__ void k_dinv(const int* __restrict__ cnt, float* __restrict__ dinv, int n) {
    int i = blockIdx.x * blockDim.x + threadIdx.x;
    if (i < n) dinv[i] = rsqrtf((float)(cnt[i] + 1));   // +1 self loop
}

// single-block exclusive scan of cnt -> off[0..n], also writes cur = off[0..n-1]
__global__ void k_scan(const int* __restrict__ cnt, int* __restrict__ off,
                       int* __restrict__ cur, int n) {
    __shared__ int sh[1024];
    __shared__ int carry_s;
    if (threadIdx.x == 0) carry_s = 0;
    __syncthreads();
    for (int base = 0; base < n; base += 1024) {
        int i = base + threadIdx.x;
        int v = (i < n) ? cnt[i] : 0;
        sh[threadIdx.x] = v;
        __syncthreads();
        #pragma unroll
        for (int s = 1; s < 1024; s <<= 1) {
            int t = (threadIdx.x >= s) ? sh[threadIdx.x - s] : 0;
            __syncthreads();
            sh[threadIdx.x] += t;
            __syncthreads();
        }
        int carry = carry_s;
        if (i < n) {
            int excl = carry + sh[threadIdx.x] - v;
            off[i] = excl;
            cur[i] = excl;
            if (i == n - 1) off[n] = carry + sh[threadIdx.x];
        }
        __syncthreads();
        if (threadIdx.x == 1023) carry_s = carry + sh[1023];
        __syncthreads();
    }
}

__global__ void k_fillcsr(const int* __restrict__ row, const int* __restrict__ col,
                          const float* __restrict__ dinv, int* cur,
                          int2* __restrict__ edge, int e) {
    int i = blockIdx.x * blockDim.x + threadIdx.x;
    if (i >= e) return;
    int s = row[i], d = col[i];
    int p = atomicAdd(&cur[d], 1);
    edge[p] = make_int2(s, __float_as_int(dinv[s]));
}

// cur = emb[:NN]; out = emb[:NN]
__global__ void k_copy2(const float4* __restrict__ src, float4* __restrict__ cur,
                        float4* __restrict__ out, int n4) {
    int i = blockIdx.x * blockDim.x + threadIdx.x;
    if (i < n4) { float4 v = src[i]; cur[i] = v; out[i] = v; }
}

// -------------------------------------------------------------- GEMM
// h[row,:] = x[row,:] @ W (128x128), W staged in 64KB smem, warp per row.
__global__ void __launch_bounds__(256)
k_gemm(const float* __restrict__ x, const float* __restrict__ W,
       float* __restrict__ h, int n) {
    extern __shared__ float4 ws4[];
    const float4* W4 = (const float4*)W;
    int tid = threadIdx.x;
    #pragma unroll
    for (int i = 0; i < 16; i++) ws4[i * 256 + tid] = W4[i * 256 + tid];
    __syncthreads();

    int warp = tid >> 5, lane = tid & 31;
    int rowbase = blockIdx.x * 64 + warp * 8;
    for (int r = 0; r < 8; r++) {
        int row = rowbase + r;
        if (row >= n) break;
        float4 xf = ((const float4*)x)[row * 32 + lane];
        float4 acc = make_float4(0.f, 0.f, 0.f, 0.f);
        #pragma unroll 8
        for (int k4 = 0; k4 < 32; k4++) {
            float x0 = __shfl_sync(0xffffffffu, xf.x, k4);
            float x1 = __shfl_sync(0xffffffffu, xf.y, k4);
            float x2 = __shfl_sync(0xffffffffu, xf.z, k4);
            float x3 = __shfl_sync(0xffffffffu, xf.w, k4);
            float4 w0 = ws4[(k4 * 4 + 0) * 32 + lane];
            acc.x += x0 * w0.x; acc.y += x0 * w0.y; acc.z += x0 * w0.z; acc.w += x0 * w0.w;
            float4 w1 = ws4[(k4 * 4 + 1) * 32 + lane];
            acc.x += x1 * w1.x; acc.y += x1 * w1.y; acc.z += x1 * w1.z; acc.w += x1 * w1.w;
            float4 w2 = ws4[(k4 * 4 + 2) * 32 + lane];
            acc.x += x2 * w2.x; acc.y += x2 * w2.y; acc.z += x2 * w2.z; acc.w += x2 * w2.w;
            float4 w3 = ws4[(k4 * 4 + 3) * 32 + lane];
            acc.x += x3 * w3.x; acc.y += x3 * w3.y; acc.z += x3 * w3.z; acc.w += x3 * w3.w;
        }
        ((float4*)h)[row * 32 + lane] = acc;
    }
}

// ---------------------------------------------------- fused CSR gather
// warp per dst node: r = dinv[d]*( dinv[d]*h[d] + Σ_in dinv[s]*h[s] ) + bias
// nxt[d]=r (unless last layer), out[d]+=r
__global__ void __launch_bounds__(256)
k_gather(const int* __restrict__ off, const int2* __restrict__ edge,
         const float* __restrict__ dinv, const float* __restrict__ h,
         const float* __restrict__ bias, float* __restrict__ nxt,
         float* __restrict__ out, int n, int write_nxt) {
    int w = (blockIdx.x * 256 + threadIdx.x) >> 5;
    if (w >= n) return;
    int lane = threadIdx.x & 31;
    const float4* h4 = (const float4*)h;

    float di = dinv[w];
    float4 hv = h4[w * 32 + lane];
    float4 acc = make_float4(hv.x * di, hv.y * di, hv.z * di, hv.w * di);

    int beg = off[w], end = off[w + 1];
    int e = beg;
    for (; e + 1 < end; e += 2) {
        int2 e0 = __ldg(edge + e);
        int2 e1 = __ldg(edge + e + 1);
        float s0 = __int_as_float(e0.y);
        float s1 = __int_as_float(e1.y);
        float4 v0 = h4[e0.x * 32 + lane];
        float4 v1 = h4[e1.x * 32 + lane];
        acc.x += v0.x * s0 + v1.x * s1;
        acc.y += v0.y * s0 + v1.y * s1;
        acc.z += v0.z * s0 + v1.z * s1;
        acc.w += v0.w * s0 + v1.w * s1;
    }
    if (e < end) {
        int2 e0 = __ldg(edge + e);
        float s0 = __int_as_float(e0.y);
        float4 v0 = h4[e0.x * 32 + lane];
        acc.x += v0.x * s0; acc.y += v0.y * s0;
        acc.z += v0.z * s0; acc.w += v0.w * s0;
    }

    float4 bv = ((const float4*)bias)[lane];
    float4 r;
    r.x = acc.x * di + bv.x;
    r.y = acc.y * di + bv.y;
    r.z = acc.z * di + bv.z;
    r.w = acc.w * di + bv.w;

    int idx = w * 32 + lane;
    if (write_nxt) ((float4*)nxt)[idx] = r;
    float4 o = ((float4*)out)[idx];
    o.x += r.x; o.y += r.y; o.z += r.z; o.w += r.w;
    ((float4*)out)[idx] = o;
}

// ================================================================ launch
extern "C" void kernel_launch(void* const* d_in, const int* in_sizes, int n_in,
                              void* d_out, int out_size) {
    const int*   edge_in = (const int*)d_in[0];   // [2, NE]
    const float* emb     = (const float*)d_in[1]; // [100001, 128]
    const float* W       = (const float*)d_in[2]; // [3,128,128]
    const float* b       = (const float*)d_in[3]; // [3,128]
    float* out = (float*)d_out;                   // [NN,128]

    const int* row = edge_in;
    const int* col = edge_in + NE;

    float *dinv, *h, *bufA, *bufB;
    int *cnt, *off, *cur;
    int2 *edg;
    cudaGetSymbolAddress((void**)&dinv, g_dinv);
    cudaGetSymbolAddress((void**)&cnt,  g_cnt);
    cudaGetSymbolAddress((void**)&off,  g_off);
    cudaGetSymbolAddress((void**)&cur,  g_cur);
    cudaGetSymbolAddress((void**)&edg,  g_edge);
    cudaGetSymbolAddress((void**)&h,    g_h);
    cudaGetSymbolAddress((void**)&bufA, g_bufA);
    cudaGetSymbolAddress((void**)&bufB, g_bufB);

    cudaFuncSetAttribute(k_gemm, cudaFuncAttributeMaxDynamicSharedMemorySize, 65536);

    const int gN  = (NN + 255) / 256;
    const int gE  = (NE + 255) / 256;
    const int g4  = (N4 + 255) / 256;
    const int gG  = (NN + 63) / 64;
    const int gW  = (NN * 32 + 255) / 256;        // warp per node

    // ---- CSR build (per call; graph-replay safe) ----
    k_zero   <<<gN, 256>>>(cnt, NN);
    k_cnt    <<<gE, 256>>>(col, cnt, NE);
    k_dinv   <<<gN, 256>>>(cnt, dinv, NN);
    k_scan   <<<1, 1024>>>(cnt, off, cur, NN);
    k_fillcsr<<<gE, 256>>>(row, col, dinv, cur, edg, NE);

    // out = curbuf = item_emb[:NN]
    k_copy2<<<g4, 256>>>((const float4*)emb, (float4*)bufA, (float4*)out, N4);

    float* curp = bufA;
    float* nxtp = bufB;
    for (int l = 0; l < 3; l++) {
        k_gemm  <<<gG, 256, 65536>>>(curp, W + l * EMB * EMB, h, NN);
        k_gather<<<gW, 256>>>(off, edg, dinv, h, b + l * EMB,
                              nxtp, out, NN, (l < 2) ? 1 : 0);
        float* t = curp; curp = nxtp; nxtp = t;
    }
}

// round 7
// speedup vs baseline: 1.2601x; 1.0305x over previous
#include <cuda_runtime.h>

#define NN 50001          // N_NODES
#define NE 800000
#define EMB 128
#define N4  (NN * 32)     // float4 per [NN,128]
#define NB_SCAN ((NN + 1023) / 1024)   // 49

// ---- scratch (device globals; no allocations allowed) ----
__device__ float g_dinv[NN];
__device__ int   g_cnt [NN];
__device__ int   g_off [NN + 1];
__device__ int   g_cur [NN];
__device__ int   g_bsum[NB_SCAN];
__device__ int2  g_edge[NE];      // (src, __float_as_int(dinv[src]))
__device__ float g_h   [NN * EMB];
__device__ float g_bufA[NN * EMB];
__device__ float g_bufB[NN * EMB];

// ---- f32x2 packed-math helpers ----
#define FMA2(d, a, b, c) \
    asm("fma.rn.f32x2 %0, %1, %2, %3;" : "=l"(d) : "l"(a), "l"(b), "l"(c))
#define PACK2(d, x) \
    asm("mov.b64 %0, {%1, %2};" : "=l"(d) : "r"(x), "r"(x))
#define UNPACK2(lo, hi, v) \
    asm("mov.b64 {%0, %1}, %2;" : "=r"(lo), "=r"(hi) : "l"(v))

// ---------------------------------------------------------------- prologue
__global__ void k_zero(int* c, int n) {
    int i = blockIdx.x * blockDim.x + threadIdx.x;
    if (i < n) c[i] = 0;
}

__global__ void k_cnt(const int* __restrict__ col, int* cnt, int e) {
    int i = blockIdx.x * blockDim.x + threadIdx.x;
    if (i < e) atomicAdd(&cnt[col[i]], 1);
}

__global__ void k_dinv(const int* __restrict__ cnt, float* __restrict__ dinv, int n) {
    int i = blockIdx.x * blockDim.x + threadIdx.x;
    if (i < n) dinv[i] = rsqrtf((float)(cnt[i] + 1));   // +1 self loop
}

// phase 1: per-block exclusive scan -> off (block-local), block totals -> bsum
__global__ void k_scan1(const int* __restrict__ cnt, int* __restrict__ loc,
                        int* __restrict__ bsum, int n) {
    __shared__ int sh[1024];
    int tid = threadIdx.x;
    int i = blockIdx.x * 1024 + tid;
    int v = (i < n) ? cnt[i] : 0;
    sh[tid] = v;
    __syncthreads();
    #pragma unroll
    for (int s = 1; s < 1024; s <<= 1) {
        int t = (tid >= s) ? sh[tid - s] : 0;
        __syncthreads();
        sh[tid] += t;
        __syncthreads();
    }
    if (i < n) loc[i] = sh[tid] - v;          // block-local exclusive
    if (tid == 1023) bsum[blockIdx.x] = sh[1023];
}

// phase 2: serial exclusive scan of 49 block sums (1 thread, trivial)
__global__ void k_scan2(int* bsum, int nb) {
    if (threadIdx.x == 0 && blockIdx.x == 0) {
        int acc = 0;
        for (int i = 0; i < nb; i++) { int v = bsum[i]; bsum[i] = acc; acc += v; }
    }
}

// phase 3: add block offsets, write off + cur, and off[n] = NE
__global__ void k_scan3(int* __restrict__ off, const int* __restrict__ bsum,
                        int* __restrict__ cur, int n) {
    int i = blockIdx.x * blockDim.x + threadIdx.x;
    if (i < n) {
        int v = off[i] + bsum[i >> 10];
        off[i] = v;
        cur[i] = v;
    }
    if (i == 0) off[n] = NE;
}

__global__ void k_fillcsr(const int* __restrict__ row, const int* __restrict__ col,
                          const float* __restrict__ dinv, int* cur,
                          int2* __restrict__ edge, int e) {
    int i = blockIdx.x * blockDim.x + threadIdx.x;
    if (i >= e) return;
    int s = row[i], d = col[i];
    int p = atomicAdd(&cur[d], 1);
    edge[p] = make_int2(s, __float_as_int(dinv[s]));
}

// out = emb[:NN]
__global__ void k_copy(const float4* __restrict__ src, float4* __restrict__ out, int n4) {
    int i = blockIdx.x * blockDim.x + threadIdx.x;
    if (i < n4) out[i] = src[i];
}

// -------------------------------------------------------------- GEMM (f32x2)
// h[row,:] = x[row,:] @ W (128x128), W staged in 64KB smem, warp per row.
__global__ void __launch_bounds__(256)
k_gemm(const float* __restrict__ x, const float* __restrict__ W,
       float* __restrict__ h, int n) {
    extern __shared__ float4 ws4[];          // W[k][4l..4l+3], 4096 float4
    const float4* W4 = (const float4*)W;
    int tid = threadIdx.x;
    #pragma unroll
    for (int i = 0; i < 16; i++) ws4[i * 256 + tid] = W4[i * 256 + tid];
    __syncthreads();

    const ulonglong2* ws8 = (const ulonglong2*)ws4;   // (w01, w23) pairs
    int warp = tid >> 5, lane = tid & 31;
    int rowbase = blockIdx.x * 64 + warp * 8;
    for (int r = 0; r < 8; r++) {
        int row = rowbase + r;
        if (row >= n) break;
        float4 xf = ((const float4*)x)[row * 32 + lane];
        unsigned long long acc01 = 0ull, acc23 = 0ull;  // (0.f,0.f) bit pattern
        #pragma unroll 8
        for (int k4 = 0; k4 < 32; k4++) {
            unsigned int x0 = __float_as_uint(__shfl_sync(0xffffffffu, xf.x, k4));
            unsigned int x1 = __float_as_uint(__shfl_sync(0xffffffffu, xf.y, k4));
            unsigned int x2 = __float_as_uint(__shfl_sync(0xffffffffu, xf.z, k4));
            unsigned int x3 = __float_as_uint(__shfl_sync(0xffffffffu, xf.w, k4));
            unsigned long long p0, p1, p2, p3;
            PACK2(p0, x0); PACK2(p1, x1); PACK2(p2, x2); PACK2(p3, x3);
            ulonglong2 w0 = ws8[(k4 * 4 + 0) * 32 + lane];
            FMA2(acc01, w0.x, p0, acc01);
            FMA2(acc23, w0.y, p0, acc23);
            ulonglong2 w1 = ws8[(k4 * 4 + 1) * 32 + lane];
            FMA2(acc01, w1.x, p1, acc01);
            FMA2(acc23, w1.y, p1, acc23);
            ulonglong2 w2 = ws8[(k4 * 4 + 2) * 32 + lane];
            FMA2(acc01, w2.x, p2, acc01);
            FMA2(acc23, w2.y, p2, acc23);
            ulonglong2 w3 = ws8[(k4 * 4 + 3) * 32 + lane];
            FMA2(acc01, w3.x, p3, acc01);
            FMA2(acc23, w3.y, p3, acc23);
        }
        unsigned int a0, a1, a2, a3;
        UNPACK2(a0, a1, acc01);
        UNPACK2(a2, a3, acc23);
        float4 acc = make_float4(__uint_as_float(a0), __uint_as_float(a1),
                                 __uint_as_float(a2), __uint_as_float(a3));
        ((float4*)h)[row * 32 + lane] = acc;
    }
}

// ---------------------------------------------------- fused CSR gather
// warp per dst node: r = dinv[d]*( dinv[d]*h[d] + Σ_in dinv[s]*h[s] ) + bias
// nxt[d]=r (unless last layer), out[d]+=r
__global__ void __launch_bounds__(256)
k_gather(const int* __restrict__ off, const int2* __restrict__ edge,
         const float* __restrict__ dinv, const float* __restrict__ h,
         const float* __restrict__ bias, float* __restrict__ nxt,
         float* __restrict__ out, int n, int write_nxt) {
    int w = (blockIdx.x * 256 + threadIdx.x) >> 5;
    if (w >= n) return;
    int lane = threadIdx.x & 31;
    const float4* h4 = (const float4*)h;

    float di = dinv[w];
    float4 hv = h4[w * 32 + lane];
    float4 acc  = make_float4(hv.x * di, hv.y * di, hv.z * di, hv.w * di);
    float4 acc2 = make_float4(0.f, 0.f, 0.f, 0.f);

    int beg = off[w], end = off[w + 1];
    int e = beg;
    for (; e + 3 < end; e += 4) {
        int2 e0 = __ldg(edge + e);
        int2 e1 = __ldg(edge + e + 1);
        int2 e2 = __ldg(edge + e + 2);
        int2 e3 = __ldg(edge + e + 3);
        float s0 = __int_as_float(e0.y), s1 = __int_as_float(e1.y);
        float s2 = __int_as_float(e2.y), s3 = __int_as_float(e3.y);
        float4 v0 = h4[e0.x * 32 + lane];
        float4 v1 = h4[e1.x * 32 + lane];
        float4 v2 = h4[e2.x * 32 + lane];
        float4 v3 = h4[e3.x * 32 + lane];
        acc.x  += v0.x * s0 + v1.x * s1;
        acc.y  += v0.y * s0 + v1.y * s1;
        acc.z  += v0.z * s0 + v1.z * s1;
        acc.w  += v0.w * s0 + v1.w * s1;
        acc2.x += v2.x * s2 + v3.x * s3;
        acc2.y += v2.y * s2 + v3.y * s3;
        acc2.z += v2.z * s2 + v3.z * s3;
        acc2.w += v2.w * s2 + v3.w * s3;
    }
    for (; e < end; e++) {
        int2 e0 = __ldg(edge + e);
        float s0 = __int_as_float(e0.y);
        float4 v0 = h4[e0.x * 32 + lane];
        acc.x += v0.x * s0; acc.y += v0.y * s0;
        acc.z += v0.z * s0; acc.w += v0.w * s0;
    }
    acc.x += acc2.x; acc.y += acc2.y; acc.z += acc2.z; acc.w += acc2.w;

    float4 bv = ((const float4*)bias)[lane];
    float4 r;
    r.x = acc.x * di + bv.x;
    r.y = acc.y * di + bv.y;
    r.z = acc.z * di + bv.z;
    r.w = acc.w * di + bv.w;

    int idx = w * 32 + lane;
    if (write_nxt) ((float4*)nxt)[idx] = r;
    float4 o = ((float4*)out)[idx];
    o.x += r.x; o.y += r.y; o.z += r.z; o.w += r.w;
    ((float4*)out)[idx] = o;
}

// ================================================================ launch
extern "C" void kernel_launch(void* const* d_in, const int* in_sizes, int n_in,
                              void* d_out, int out_size) {
    const int*   edge_in = (const int*)d_in[0];   // [2, NE]
    const float* emb     = (const float*)d_in[1]; // [100001, 128]
    const float* W       = (const float*)d_in[2]; // [3,128,128]
    const float* b       = (const float*)d_in[3]; // [3,128]
    float* out = (float*)d_out;                   // [NN,128]

    const int* row = edge_in;
    const int* col = edge_in + NE;

    float *dinv, *h, *bufA, *bufB;
    int *cnt, *off, *cur, *bsum;
    int2 *edg;
    cudaGetSymbolAddress((void**)&dinv, g_dinv);
    cudaGetSymbolAddress((void**)&cnt,  g_cnt);
    cudaGetSymbolAddress((void**)&off,  g_off);
    cudaGetSymbolAddress((void**)&cur,  g_cur);
    cudaGetSymbolAddress((void**)&bsum, g_bsum);
    cudaGetSymbolAddress((void**)&edg,  g_edge);
    cudaGetSymbolAddress((void**)&h,    g_h);
    cudaGetSymbolAddress((void**)&bufA, g_bufA);
    cudaGetSymbolAddress((void**)&bufB, g_bufB);

    cudaFuncSetAttribute(k_gemm, cudaFuncAttributeMaxDynamicSharedMemorySize, 65536);

    const int gN  = (NN + 255) / 256;
    const int gE  = (NE + 255) / 256;
    const int g4  = (N4 + 255) / 256;
    const int gG  = (NN + 63) / 64;
    const int gW  = (NN * 32 + 255) / 256;        // warp per node

    // ---- CSR build ----
    k_zero   <<<gN, 256>>>(cnt, NN);
    k_cnt    <<<gE, 256>>>(col, cnt, NE);
    k_dinv   <<<gN, 256>>>(cnt, dinv, NN);
    k_scan1  <<<NB_SCAN, 1024>>>(cnt, off, bsum, NN);
    k_scan2  <<<1, 32>>>(bsum, NB_SCAN);
    k_scan3  <<<gN, 256>>>(off, bsum, cur, NN);
    k_fillcsr<<<gE, 256>>>(row, col, dinv, cur, edg, NE);

    // out = item_emb[:NN]
    k_copy<<<g4, 256>>>((const float4*)emb, (float4*)out, N4);

    const float* curp = emb;       // layer 1 reads emb directly
    float* nxtp = bufA;
    float* altp = bufB;
    for (int l = 0; l < 3; l++) {
        k_gemm  <<<gG, 256, 65536>>>(curp, W + l * EMB * EMB, h, NN);
        k_gather<<<gW, 256>>>(off, edg, dinv, h, b + l * EMB,
                              nxtp, out, NN, (l < 2) ? 1 : 0);
        curp = nxtp;
        float* t = nxtp; nxtp = altp; altp = t;
    }
}

// round 9
// speedup vs baseline: 2.3677x; 1.8790x over previous
#include <cuda_runtime.h>

#define NN 50001          // N_NODES
#define NE 800000
#define EMB 128
#define N4  (NN * 32)     // float4 per [NN,128]
#define NB_SCAN ((NN + 1023) / 1024)   // 49

#define GROWS 96          // rows per gemm block
#define GTHREADS 384

// ---- scratch (device globals; no allocations allowed) ----
__device__ float g_dinv[NN];
__device__ int   g_cnt [NN];
__device__ int   g_off [NN + 1];
__device__ int   g_cur [NN];
__device__ int   g_bsum[NB_SCAN];
__device__ int2  g_edge[NE];      // (src, __float_as_int(dinv[src]))
__device__ float g_h   [NN * EMB];
__device__ float g_bufA[NN * EMB];
__device__ float g_bufB[NN * EMB];

// ---- f32x2 packed-math helpers ----
#define FMA2(d, a, b, c) \
    asm("fma.rn.f32x2 %0, %1, %2, %3;" : "=l"(d) : "l"(a), "l"(b), "l"(c))
#define UNPACK2(lo, hi, v) \
    asm("mov.b64 {%0, %1}, %2;" : "=r"(lo), "=r"(hi) : "l"(v))

__device__ __forceinline__ unsigned long long dup32(float f) {
    unsigned int u = __float_as_uint(f);
    return (unsigned long long)u | ((unsigned long long)u << 32);
}

// ---------------------------------------------------------------- prologue
__global__ void k_zero(int* c, int n) {
    int i = blockIdx.x * blockDim.x + threadIdx.x;
    if (i < n) c[i] = 0;
}

__global__ void k_cnt(const int* __restrict__ col, int* cnt, int e) {
    int i = blockIdx.x * blockDim.x + threadIdx.x;
    if (i < e) atomicAdd(&cnt[col[i]], 1);
}

__global__ void k_dinv(const int* __restrict__ cnt, float* __restrict__ dinv, int n) {
    int i = blockIdx.x * blockDim.x + threadIdx.x;
    if (i < n) dinv[i] = rsqrtf((float)(cnt[i] + 1));   // +1 self loop
}

__global__ void k_scan1(const int* __restrict__ cnt, int* __restrict__ loc,
                        int* __restrict__ bsum, int n) {
    __shared__ int sh[1024];
    int tid = threadIdx.x;
    int i = blockIdx.x * 1024 + tid;
    int v = (i < n) ? cnt[i] : 0;
    sh[tid] = v;
    __syncthreads();
    #pragma unroll
    for (int s = 1; s < 1024; s <<= 1) {
        int t = (tid >= s) ? sh[tid - s] : 0;
        __syncthreads();
        sh[tid] += t;
        __syncthreads();
    }
    if (i < n) loc[i] = sh[tid] - v;          // block-local exclusive
    if (tid == 1023) bsum[blockIdx.x] = sh[1023];
}

__global__ void k_scan2(int* bsum, int nb) {
    if (threadIdx.x == 0 && blockIdx.x == 0) {
        int acc = 0;
        for (int i = 0; i < nb; i++) { int v = bsum[i]; bsum[i] = acc; acc += v; }
    }
}

__global__ void k_scan3(int* __restrict__ off, const int* __restrict__ bsum,
                        int* __restrict__ cur, int n) {
    int i = blockIdx.x * blockDim.x + threadIdx.x;
    if (i < n) {
        int v = off[i] + bsum[i >> 10];
        off[i] = v;
        cur[i] = v;
    }
    if (i == 0) off[n] = NE;
}

__global__ void k_fillcsr(const int* __restrict__ row, const int* __restrict__ col,
                          const float* __restrict__ dinv, int* cur,
                          int2* __restrict__ edge, int e) {
    int i = blockIdx.x * blockDim.x + threadIdx.x;
    if (i >= e) return;
    int s = row[i], d = col[i];
    int p = atomicAdd(&cur[d], 1);
    edge[p] = make_int2(s, __float_as_int(dinv[s]));
}

// -------------------------------------------------------------- GEMM v3
// h = x @ W.  W (64KB) + x-tile duplicated-f32x2 (96KB) staged in smem.
// 384 threads = 12 warps; each warp computes 8 rows, amortizing W loads 8x.
__global__ void __launch_bounds__(GTHREADS)
k_gemm(const float* __restrict__ x, const float* __restrict__ W,
       float* __restrict__ h, int n) {
    extern __shared__ unsigned long long sm[];
    float4*    wsf = (float4*)sm;                          // [4096] = W row-major
    ulonglong2* ws = (ulonglong2*)sm;                      // alias: ws[k*32+l]
    unsigned long long* xs = sm + 8192;                    // xs[row*128 + k] = dup(x)
    int tid = threadIdx.x;
    int base = blockIdx.x * GROWS;

    // stage W
    const float4* W4 = (const float4*)W;
    #pragma unroll
    for (int i = tid; i < 4096; i += GTHREADS) wsf[i] = W4[i];

    // stage x rows, duplicated per element
    const float4* x4 = (const float4*)x;
    #pragma unroll
    for (int i = tid; i < GROWS * 32; i += GTHREADS) {
        int r = i >> 5, c = i & 31;
        int rg = base + r; if (rg >= n) rg = n - 1;
        float4 v = x4[rg * 32 + c];
        ulonglong2* dst = (ulonglong2*)(xs + r * 128) + 2 * c;
        ulonglong2 a; a.x = dup32(v.x); a.y = dup32(v.y);
        ulonglong2 b; b.x = dup32(v.z); b.y = dup32(v.w);
        dst[0] = a; dst[1] = b;
    }
    __syncthreads();

    int warp = tid >> 5, lane = tid & 31;
    int rbase = warp * 8;                 // local rows rbase..rbase+7

    unsigned long long acc01[8], acc23[8];
    #pragma unroll
    for (int r = 0; r < 8; r++) { acc01[r] = 0ull; acc23[r] = 0ull; }

    #pragma unroll 2
    for (int k4 = 0; k4 < 32; k4++) {
        ulonglong2 w0 = ws[(k4 * 4 + 0) * 32 + lane];
        ulonglong2 w1 = ws[(k4 * 4 + 1) * 32 + lane];
        ulonglong2 w2 = ws[(k4 * 4 + 2) * 32 + lane];
        ulonglong2 w3 = ws[(k4 * 4 + 3) * 32 + lane];
        #pragma unroll
        for (int r = 0; r < 8; r++) {
            const ulonglong2* xp = (const ulonglong2*)(xs + (rbase + r) * 128) + 2 * k4;
            ulonglong2 xa = xp[0];        // (dup x[4k4+0], dup x[4k4+1])
            ulonglong2 xb = xp[1];        // (dup x[4k4+2], dup x[4k4+3])
            FMA2(acc01[r], w0.x, xa.x, acc01[r]);
            FMA2(acc23[r], w0.y, xa.x, acc23[r]);
            FMA2(acc01[r], w1.x, xa.y, acc01[r]);
            FMA2(acc23[r], w1.y, xa.y, acc23[r]);
            FMA2(acc01[r], w2.x, xb.x, acc01[r]);
            FMA2(acc23[r], w2.y, xb.x, acc23[r]);
            FMA2(acc01[r], w3.x, xb.y, acc01[r]);
            FMA2(acc23[r], w3.y, xb.y, acc23[r]);
        }
    }

    #pragma unroll
    for (int r = 0; r < 8; r++) {
        int rg = base + rbase + r;
        if (rg < n) {
            unsigned int a0, a1, a2, a3;
            UNPACK2(a0, a1, acc01[r]);
            UNPACK2(a2, a3, acc23[r]);
            float4 o = make_float4(__uint_as_float(a0), __uint_as_float(a1),
                                   __uint_as_float(a2), __uint_as_float(a3));
            ((float4*)h)[rg * 32 + lane] = o;
        }
    }
}

// ---------------------------------------------------- fused CSR gather
// warp per dst node: r = dinv[d]*( dinv[d]*h[d] + sum_in dinv[s]*h[s] ) + bias
// mode 0: dst[d] = r             (intermediate layer)
// mode 1: dst[d] = r + e1 + e2 + e3   (last layer: out = emb + l1 + l2 + r)
__global__ void __launch_bounds__(256)
k_gather(const int* __restrict__ off, const int2* __restrict__ edge,
         const float* __restrict__ dinv, const float* __restrict__ h,
         const float* __restrict__ bias, float* __restrict__ dst,
         const float4* __restrict__ e1, const float4* __restrict__ e2,
         const float4* __restrict__ e3, int n, int mode) {
    int w = (blockIdx.x * 256 + threadIdx.x) >> 5;
    if (w >= n) return;
    int lane = threadIdx.x & 31;
    const float4* h4 = (const float4*)h;

    float di = dinv[w];
    float4 hv = h4[w * 32 + lane];
    float4 acc  = make_float4(hv.x * di, hv.y * di, hv.z * di, hv.w * di);
    float4 acc2 = make_float4(0.f, 0.f, 0.f, 0.f);

    int beg = off[w], end = off[w + 1];
    int e = beg;
    for (; e + 3 < end; e += 4) {
        int2 e0 = __ldg(edge + e);
        int2 ee1 = __ldg(edge + e + 1);
        int2 ee2 = __ldg(edge + e + 2);
        int2 ee3 = __ldg(edge + e + 3);
        float s0 = __int_as_float(e0.y), s1 = __int_as_float(ee1.y);
        float s2 = __int_as_float(ee2.y), s3 = __int_as_float(ee3.y);
        float4 v0 = h4[e0.x * 32 + lane];
        float4 v1 = h4[ee1.x * 32 + lane];
        float4 v2 = h4[ee2.x * 32 + lane];
        float4 v3 = h4[ee3.x * 32 + lane];
        acc.x  += v0.x * s0 + v1.x * s1;
        acc.y  += v0.y * s0 + v1.y * s1;
        acc.z  += v0.z * s0 + v1.z * s1;
        acc.w  += v0.w * s0 + v1.w * s1;
        acc2.x += v2.x * s2 + v3.x * s3;
        acc2.y += v2.y * s2 + v3.y * s3;
        acc2.z += v2.z * s2 + v3.z * s3;
        acc2.w += v2.w * s2 + v3.w * s3;
    }
    for (; e < end; e++) {
        int2 e0 = __ldg(edge + e);
        float s0 = __int_as_float(e0.y);
        float4 v0 = h4[e0.x * 32 + lane];
        acc.x += v0.x * s0; acc.y += v0.y * s0;
        acc.z += v0.z * s0; acc.w += v0.w * s0;
    }
    acc.x += acc2.x; acc.y += acc2.y; acc.z += acc2.z; acc.w += acc2.w;

    float4 bv = ((const float4*)bias)[lane];
    float4 r;
    r.x = acc.x * di + bv.x;
    r.y = acc.y * di + bv.y;
    r.z = acc.z * di + bv.z;
    r.w = acc.w * di + bv.w;

    int idx = w * 32 + lane;
    if (mode == 1) {
        float4 a = e1[idx], b2 = e2[idx], c = e3[idx];
        r.x += a.x + b2.x + c.x;
        r.y += a.y + b2.y + c.y;
        r.z += a.z + b2.z + c.z;
        r.w += a.w + b2.w + c.w;
    }
    ((float4*)dst)[idx] = r;
}

// ================================================================ launch
extern "C" void kernel_launch(void* const* d_in, const int* in_sizes, int n_in,
                              void* d_out, int out_size) {
    const int*   edge_in = (const int*)d_in[0];   // [2, NE]
    const float* emb     = (const float*)d_in[1]; // [100001, 128]
    const float* W       = (const float*)d_in[2]; // [3,128,128]
    const float* b       = (const float*)d_in[3]; // [3,128]
    float* out = (float*)d_out;                   // [NN,128]

    const int* row = edge_in;
    const int* col = edge_in + NE;

    float *dinv, *h, *bufA, *bufB;
    int *cnt, *off, *cur, *bsum;
    int2 *edg;
    cudaGetSymbolAddress((void**)&dinv, g_dinv);
    cudaGetSymbolAddress((void**)&cnt,  g_cnt);
    cudaGetSymbolAddress((void**)&off,  g_off);
    cudaGetSymbolAddress((void**)&cur,  g_cur);
    cudaGetSymbolAddress((void**)&bsum, g_bsum);
    cudaGetSymbolAddress((void**)&edg,  g_edge);
    cudaGetSymbolAddress((void**)&h,    g_h);
    cudaGetSymbolAddress((void**)&bufA, g_bufA);
    cudaGetSymbolAddress((void**)&bufB, g_bufB);

    const int SMEM_G = 65536 + GROWS * 128 * 8;   // W + dup'd x tile = 163840
    cudaFuncSetAttribute(k_gemm, cudaFuncAttributeMaxDynamicSharedMemorySize, SMEM_G);

    const int gN  = (NN + 255) / 256;
    const int gE  = (NE + 255) / 256;
    const int gG  = (NN + GROWS - 1) / GROWS;
    const int gW  = (NN * 32 + 255) / 256;        // warp per node

    // ---- CSR build ----
    k_zero   <<<gN, 256>>>(cnt, NN);
    k_cnt    <<<gE, 256>>>(col, cnt, NE);
    k_dinv   <<<gN, 256>>>(cnt, dinv, NN);
    k_scan1  <<<NB_SCAN, 1024>>>(cnt, off, bsum, NN);
    k_scan2  <<<1, 32>>>(bsum, NB_SCAN);
    k_scan3  <<<gN, 256>>>(off, bsum, cur, NN);
    k_fillcsr<<<gE, 256>>>(row, col, dinv, cur, edg, NE);

    // layer 0: emb -> h -> bufA
    k_gemm  <<<gG, GTHREADS, SMEM_G>>>(emb, W + 0 * EMB * EMB, h, NN);
    k_gather<<<gW, 256>>>(off, edg, dinv, h, b + 0 * EMB, bufA,
                          (const float4*)emb, (const float4*)emb, (const float4*)emb, NN, 0);
    // layer 1: bufA -> h -> bufB
    k_gemm  <<<gG, GTHREADS, SMEM_G>>>(bufA, W + 1 * EMB * EMB, h, NN);
    k_gather<<<gW, 256>>>(off, edg, dinv, h, b + 1 * EMB, bufB,
                          (const float4*)emb, (const float4*)emb, (const float4*)emb, NN, 0);
    // layer 2: bufB -> h -> out = r + emb + bufA + bufB
    k_gemm  <<<gG, GTHREADS, SMEM_G>>>(bufB, W + 2 * EMB * EMB, h, NN);
    k_gather<<<gW, 256>>>(off, edg, dinv, h, b + 2 * EMB, out,
                          (const float4*)emb, (const float4*)bufA, (const float4*)bufB, NN, 1);
}

// round 11
// speedup vs baseline: 2.5739x; 1.0871x over previous
#include <cuda_runtime.h>
#include <cuda_fp16.h>

#define NN 50001          // N_NODES
#define NE 800000
#define EMB 128
#define NB_SCAN ((NN + 1023) / 1024)   // 49

#define GROWS 96          // rows per gemm block
#define GTHREADS 384

// ---- scratch (device globals; no allocations allowed) ----
__device__ float g_dinv[NN];
__device__ int   g_cnt [NN];
__device__ int   g_off [NN + 1];
__device__ int   g_cur [NN];
__device__ int   g_bsum[NB_SCAN];
__device__ int2  g_edge[NE];          // (src, __float_as_int(dinv[src]))
__device__ __half g_h  [NN * EMB];    // fp16 intermediate (gather-traffic halved)
__device__ float g_bufA[NN * EMB];
__device__ float g_bufB[NN * EMB];

// ---- f32x2 packed-math helpers ----
#define FMA2(d, a, b, c) \
    asm("fma.rn.f32x2 %0, %1, %2, %3;" : "=l"(d) : "l"(a), "l"(b), "l"(c))
#define UNPACK2(lo, hi, v) \
    asm("mov.b64 {%0, %1}, %2;" : "=r"(lo), "=r"(hi) : "l"(v))

__device__ __forceinline__ unsigned long long dup32(float f) {
    unsigned int u = __float_as_uint(f);
    return (unsigned long long)u | ((unsigned long long)u << 32);
}

// ---------------------------------------------------------------- prologue
__global__ void k_zero(int* c, int n) {
    int i = blockIdx.x * blockDim.x + threadIdx.x;
    if (i < n) c[i] = 0;
}

__global__ void k_cnt(const int* __restrict__ col, int* cnt, int e) {
    int i = blockIdx.x * blockDim.x + threadIdx.x;
    if (i < e) atomicAdd(&cnt[col[i]], 1);
}

__global__ void k_scan1(const int* __restrict__ cnt, int* __restrict__ loc,
                        int* __restrict__ bsum, int n) {
    __shared__ int sh[1024];
    int tid = threadIdx.x;
    int i = blockIdx.x * 1024 + tid;
    int v = (i < n) ? cnt[i] : 0;
    sh[tid] = v;
    __syncthreads();
    #pragma unroll
    for (int s = 1; s < 1024; s <<= 1) {
        int t = (tid >= s) ? sh[tid - s] : 0;
        __syncthreads();
        sh[tid] += t;
        __syncthreads();
    }
    if (i < n) loc[i] = sh[tid] - v;          // block-local exclusive
    if (tid == 1023) bsum[blockIdx.x] = sh[1023];
}

__global__ void k_scan2(int* bsum, int nb) {
    if (threadIdx.x == 0 && blockIdx.x == 0) {
        int acc = 0;
        for (int i = 0; i < nb; i++) { int v = bsum[i]; bsum[i] = acc; acc += v; }
    }
}

// add block offsets, write off + cur, dinv, off[n]=NE
__global__ void k_scan3(int* __restrict__ off, const int* __restrict__ bsum,
                        int* __restrict__ cur, const int* __restrict__ cnt,
                        float* __restrict__ dinv, int n) {
    int i = blockIdx.x * blockDim.x + threadIdx.x;
    if (i < n) {
        int v = off[i] + bsum[i >> 10];
        off[i] = v;
        cur[i] = v;
        dinv[i] = rsqrtf((float)(cnt[i] + 1));   // +1 self loop
    }
    if (i == 0) off[n] = NE;
}

__global__ void k_fillcsr(const int* __restrict__ row, const int* __restrict__ col,
                          const float* __restrict__ dinv, int* cur,
                          int2* __restrict__ edge, int e) {
    int i = blockIdx.x * blockDim.x + threadIdx.x;
    if (i >= e) return;
    int s = row[i], d = col[i];
    int p = atomicAdd(&cur[d], 1);
    edge[p] = make_int2(s, __float_as_int(dinv[s]));
}

// -------------------------------------------------------------- GEMM v4
// h(fp16) = x(fp32) @ W.  W (64KB) + x-tile duplicated-f32x2 (96KB) in smem.
// 384 threads = 12 warps; each warp computes 8 rows, amortizing W loads 8x.
__global__ void __launch_bounds__(GTHREADS)
k_gemm(const float* __restrict__ x, const float* __restrict__ W,
       __half* __restrict__ h, int n) {
    extern __shared__ unsigned long long sm[];
    float4*    wsf = (float4*)sm;                          // [4096] = W row-major
    ulonglong2* ws = (ulonglong2*)sm;                      // alias: ws[k*32+l]
    unsigned long long* xs = sm + 8192;                    // xs[row*128 + k] = dup(x)
    int tid = threadIdx.x;
    int base = blockIdx.x * GROWS;

    // stage W
    const float4* W4 = (const float4*)W;
    #pragma unroll
    for (int i = tid; i < 4096; i += GTHREADS) wsf[i] = W4[i];

    // stage x rows, duplicated per element
    const float4* x4 = (const float4*)x;
    #pragma unroll
    for (int i = tid; i < GROWS * 32; i += GTHREADS) {
        int r = i >> 5, c = i & 31;
        int rg = base + r; if (rg >= n) rg = n - 1;
        float4 v = x4[rg * 32 + c];
        ulonglong2* dst = (ulonglong2*)(xs + r * 128) + 2 * c;
        ulonglong2 a; a.x = dup32(v.x); a.y = dup32(v.y);
        ulonglong2 b; b.x = dup32(v.z); b.y = dup32(v.w);
        dst[0] = a; dst[1] = b;
    }
    __syncthreads();

    int warp = tid >> 5, lane = tid & 31;
    int rbase = warp * 8;                 // local rows rbase..rbase+7

    unsigned long long acc01[8], acc23[8];
    #pragma unroll
    for (int r = 0; r < 8; r++) { acc01[r] = 0ull; acc23[r] = 0ull; }

    #pragma unroll 2
    for (int k4 = 0; k4 < 32; k4++) {
        ulonglong2 w0 = ws[(k4 * 4 + 0) * 32 + lane];
        ulonglong2 w1 = ws[(k4 * 4 + 1) * 32 + lane];
        ulonglong2 w2 = ws[(k4 * 4 + 2) * 32 + lane];
        ulonglong2 w3 = ws[(k4 * 4 + 3) * 32 + lane];
        #pragma unroll
        for (int r = 0; r < 8; r++) {
            const ulonglong2* xp = (const ulonglong2*)(xs + (rbase + r) * 128) + 2 * k4;
            ulonglong2 xa = xp[0];        // (dup x[4k4+0], dup x[4k4+1])
            ulonglong2 xb = xp[1];        // (dup x[4k4+2], dup x[4k4+3])
            FMA2(acc01[r], w0.x, xa.x, acc01[r]);
            FMA2(acc23[r], w0.y, xa.x, acc23[r]);
            FMA2(acc01[r], w1.x, xa.y, acc01[r]);
            FMA2(acc23[r], w1.y, xa.y, acc23[r]);
            FMA2(acc01[r], w2.x, xb.x, acc01[r]);
            FMA2(acc23[r], w2.y, xb.x, acc23[r]);
            FMA2(acc01[r], w3.x, xb.y, acc01[r]);
            FMA2(acc23[r], w3.y, xb.y, acc23[r]);
        }
    }

    #pragma unroll
    for (int r = 0; r < 8; r++) {
        int rg = base + rbase + r;
        if (rg < n) {
            unsigned int a0, a1, a2, a3;
            UNPACK2(a0, a1, acc01[r]);
            UNPACK2(a2, a3, acc23[r]);
            __half2 hx = __floats2half2_rn(__uint_as_float(a0), __uint_as_float(a1));
            __half2 hy = __floats2half2_rn(__uint_as_float(a2), __uint_as_float(a3));
            uint2 o;
            o.x = *(unsigned int*)&hx;
            o.y = *(unsigned int*)&hy;
            ((uint2*)h)[rg * 32 + lane] = o;
        }
    }
}

// ---------------------------------------------------- fused CSR gather
// warp per dst node: r = dinv[d]*( dinv[d]*h[d] + sum_in dinv[s]*h[s] ) + bias
// mode 0: dst[d] = r             (intermediate layer)
// mode 1: dst[d] = r + e1 + e2 + e3   (last layer: out = emb + l1 + l2 + r)
__device__ __forceinline__ float4 h4_load(const uint2* __restrict__ h2, int idx) {
    uint2 raw = __ldg(h2 + idx);
    __half2 a = *(__half2*)&raw.x;
    __half2 b = *(__half2*)&raw.y;
    float2 fa = __half22float2(a), fb = __half22float2(b);
    return make_float4(fa.x, fa.y, fb.x, fb.y);
}

__global__ void __launch_bounds__(256)
k_gather(const int* __restrict__ off, const int2* __restrict__ edge,
         const float* __restrict__ dinv, const __half* __restrict__ h,
         const float* __restrict__ bias, float* __restrict__ dst,
         const float4* __restrict__ e1, const float4* __restrict__ e2,
         const float4* __restrict__ e3, int n, int mode) {
    int w = (blockIdx.x * 256 + threadIdx.x) >> 5;
    if (w >= n) return;
    int lane = threadIdx.x & 31;
    const uint2* h2 = (const uint2*)h;

    float di = dinv[w];
    float4 hv = h4_load(h2, w * 32 + lane);
    float4 acc  = make_float4(hv.x * di, hv.y * di, hv.z * di, hv.w * di);
    float4 acc2 = make_float4(0.f, 0.f, 0.f, 0.f);

    int beg = off[w], end = off[w + 1];
    int e = beg;
    for (; e + 3 < end; e += 4) {
        int2 e0 = __ldg(edge + e);
        int2 ee1 = __ldg(edge + e + 1);
        int2 ee2 = __ldg(edge + e + 2);
        int2 ee3 = __ldg(edge + e + 3);
        float s0 = __int_as_float(e0.y), s1 = __int_as_float(ee1.y);
        float s2 = __int_as_float(ee2.y), s3 = __int_as_float(ee3.y);
        float4 v0 = h4_load(h2, e0.x * 32 + lane);
        float4 v1 = h4_load(h2, ee1.x * 32 + lane);
        float4 v2 = h4_load(h2, ee2.x * 32 + lane);
        float4 v3 = h4_load(h2, ee3.x * 32 + lane);
        acc.x  += v0.x * s0 + v1.x * s1;
        acc.y  += v0.y * s0 + v1.y * s1;
        acc.z  += v0.z * s0 + v1.z * s1;
        acc.w  += v0.w * s0 + v1.w * s1;
        acc2.x += v2.x * s2 + v3.x * s3;
        acc2.y += v2.y * s2 + v3.y * s3;
        acc2.z += v2.z * s2 + v3.z * s3;
        acc2.w += v2.w * s2 + v3.w * s3;
    }
    for (; e < end; e++) {
        int2 e0 = __ldg(edge + e);
        float s0 = __int_as_float(e0.y);
        float4 v0 = h4_load(h2, e0.x * 32 + lane);
        acc.x += v0.x * s0; acc.y += v0.y * s0;
        acc.z += v0.z * s0; acc.w += v0.w * s0;
    }
    acc.x += acc2.x; acc.y += acc2.y; acc.z += acc2.z; acc.w += acc2.w;

    float4 bv = ((const float4*)bias)[lane];
    float4 r;
    r.x = acc.x * di + bv.x;
    r.y = acc.y * di + bv.y;
    r.z = acc.z * di + bv.z;
    r.w = acc.w * di + bv.w;

    int idx = w * 32 + lane;
    if (mode == 1) {
        float4 a = e1[idx], b2 = e2[idx], c = e3[idx];
        r.x += a.x + b2.x + c.x;
        r.y += a.y + b2.y + c.y;
        r.z += a.z + b2.z + c.z;
        r.w += a.w + b2.w + c.w;
    }
    ((float4*)dst)[idx] = r;
}

// ================================================================ launch
extern "C" void kernel_launch(void* const* d_in, const int* in_sizes, int n_in,
                              void* d_out, int out_size) {
    const int*   edge_in = (const int*)d_in[0];   // [2, NE]
    const float* emb     = (const float*)d_in[1]; // [100001, 128]
    const float* W       = (const float*)d_in[2]; // [3,128,128]
    const float* b       = (const float*)d_in[3]; // [3,128]
    float* out = (float*)d_out;                   // [NN,128]

    const int* row = edge_in;
    const int* col = edge_in + NE;

    float *dinv, *bufA, *bufB;
    __half* h;
    int *cnt, *off, *cur, *bsum;
    int2 *edg;
    cudaGetSymbolAddress((void**)&dinv, g_dinv);
    cudaGetSymbolAddress((void**)&cnt,  g_cnt);
    cudaGetSymbolAddress((void**)&off,  g_off);
    cudaGetSymbolAddress((void**)&cur,  g_cur);
    cudaGetSymbolAddress((void**)&bsum, g_bsum);
    cudaGetSymbolAddress((void**)&edg,  g_edge);
    cudaGetSymbolAddress((void**)&h,    g_h);
    cudaGetSymbolAddress((void**)&bufA, g_bufA);
    cudaGetSymbolAddress((void**)&bufB, g_bufB);

    const int SMEM_G = 65536 + GROWS * 128 * 8;   // W + dup'd x tile = 163840
    cudaFuncSetAttribute(k_gemm, cudaFuncAttributeMaxDynamicSharedMemorySize, SMEM_G);

    const int gN  = (NN + 255) / 256;
    const int gE  = (NE + 255) / 256;
    const int gG  = (NN + GROWS - 1) / GROWS;
    const int gW  = (NN * 32 + 255) / 256;        // warp per node

    // ---- CSR build ----
    k_zero   <<<gN, 256>>>(cnt, NN);
    k_cnt    <<<gE, 256>>>(col, cnt, NE);
    k_scan1  <<<NB_SCAN, 1024>>>(cnt, off, bsum, NN);
    k_scan2  <<<1, 32>>>(bsum, NB_SCAN);
    k_scan3  <<<gN, 256>>>(off, bsum, cur, cnt, dinv, NN);
    k_fillcsr<<<gE, 256>>>(row, col, dinv, cur, edg, NE);

    // layer 0: emb -> h -> bufA
    k_gemm  <<<gG, GTHREADS, SMEM_G>>>(emb, W + 0 * EMB * EMB, h, NN);
    k_gather<<<gW, 256>>>(off, edg, dinv, h, b + 0 * EMB, bufA,
                          (const float4*)emb, (const float4*)emb, (const float4*)emb, NN, 0);
    // layer 1: bufA -> h -> bufB
    k_gemm  <<<gG, GTHREADS, SMEM_G>>>(bufA, W + 1 * EMB * EMB, h, NN);
    k_gather<<<gW, 256>>>(off, edg, dinv, h, b + 1 * EMB, bufB,
                          (const float4*)emb, (const float4*)emb, (const float4*)emb, NN, 0);
    // layer 2: bufB -> h -> out = r + emb + bufA + bufB
    k_gemm  <<<gG, GTHREADS, SMEM_G>>>(bufB, W + 2 * EMB * EMB, h, NN);
    k_gather<<<gW, 256>>>(off, edg, dinv, h, b + 2 * EMB, out,
                          (const float4*)emb, (const float4*)bufA, (const float4*)bufB, NN, 1);
}

// round 17
// speedup vs baseline: 2.7561x; 1.0708x over previous
#include <cuda_runtime.h>
#include <cuda_fp16.h>
#include <cstdint>

#define NN 50001          // N_NODES
#define NE 800000
#define EMB 128
#define NB_SCAN ((NN + 1023) / 1024)   // 49

#define GROWS 96          // rows per gemm block
#define GTHREADS 384

// ---- scratch (device globals; no allocations allowed) ----
__device__ float g_dinv[NN];
__device__ int   g_cnt [NN];
__device__ int   g_off [NN + 1];
__device__ int   g_cur [NN];
__device__ int   g_bsum[NB_SCAN];
__device__ int2  g_edge[NE];          // (src, bits(dinv[src]))
__device__ __half g_h   [NN * EMB];   // fp16 GEMM output
__device__ __half g_bufA[NN * EMB];   // fp16 layer-1 embedding
__device__ __half g_bufB[NN * EMB];   // fp16 layer-2 embedding

// ---- f32x2 packed-math helpers ----
#define FMA2(d, a, b, c) \
    asm("fma.rn.f32x2 %0, %1, %2, %3;" : "=l"(d) : "l"(a), "l"(b), "l"(c))
#define UNPACK2(lo, hi, v) \
    asm("mov.b64 {%0, %1}, %2;" : "=r"(lo), "=r"(hi) : "l"(v))

__device__ __forceinline__ unsigned long long dup32(float f) {
    unsigned int u = __float_as_uint(f);
    return (unsigned long long)u | ((unsigned long long)u << 32);
}

// ---------------------------------------------------------------- prologue
__global__ void k_zero(int* c, int n) {
    int i = blockIdx.x * blockDim.x + threadIdx.x;
    if (i < n) c[i] = 0;
}

__global__ void k_cnt(const int* __restrict__ col, int* cnt, int e) {
    int i = blockIdx.x * blockDim.x + threadIdx.x;
    if (i < e) atomicAdd(&cnt[col[i]], 1);
}

__global__ void k_scan1(const int* __restrict__ cnt, int* __restrict__ loc,
                        int* __restrict__ bsum, int n) {
    __shared__ int sh[1024];
    int tid = threadIdx.x;
    int i = blockIdx.x * 1024 + tid;
    int v = (i < n) ? cnt[i] : 0;
    sh[tid] = v;
    __syncthreads();
    #pragma unroll
    for (int s = 1; s < 1024; s <<= 1) {
        int t = (tid >= s) ? sh[tid - s] : 0;
        __syncthreads();
        sh[tid] += t;
        __syncthreads();
    }
    if (i < n) loc[i] = sh[tid] - v;          // block-local exclusive
    if (tid == 1023) bsum[blockIdx.x] = sh[1023];
}

// add cross-block prefix (computed in-block from bsum), write off+cur+dinv, off[n]=NE
__global__ void k_scan3(int* __restrict__ off, const int* __restrict__ bsum,
                        int* __restrict__ cur, const int* __restrict__ cnt,
                        float* __restrict__ dinv, int n) {
    __shared__ int pre_s;
    int nbpre = blockIdx.x >> 2;        // this 256-block lies in 1024-chunk (bid>>2)
    if (threadIdx.x < 32) {
        int v = (threadIdx.x < nbpre) ? bsum[threadIdx.x] : 0;
        if (threadIdx.x + 32 < nbpre) v += bsum[threadIdx.x + 32];
        #pragma unroll
        for (int s = 16; s; s >>= 1) v += __shfl_down_sync(0xffffffffu, v, s);
        if (threadIdx.x == 0) pre_s = v;
    }
    __syncthreads();
    int pre = pre_s;
    int i = blockIdx.x * 256 + threadIdx.x;
    if (i < n) {
        int v = off[i] + pre;
        off[i] = v;
        cur[i] = v;
        dinv[i] = rsqrtf((float)(cnt[i] + 1));   // +1 self loop
    }
    if (i == 0) off[n] = NE;
}

__global__ void k_fillcsr(const int* __restrict__ row, const int* __restrict__ col,
                          const float* __restrict__ dinv, int* cur,
                          int2* __restrict__ edge, int e) {
    int i = blockIdx.x * blockDim.x + threadIdx.x;
    if (i >= e) return;
    int s = row[i], d = col[i];
    int p = atomicAdd(&cur[d], 1);
    edge[p] = make_int2(s, __float_as_int(dinv[s]));
}

// -------------------------------------------------------------- GEMM (FMA2)
// h(fp16) = x @ W.  W (64KB) + x-tile duplicated-f32x2 (96KB) in smem.
// 384 threads = 12 warps; each warp computes 8 rows, amortizing W loads 8x.
// FP16IN: x rows are fp16 (bufA/bufB); else fp32 (emb).
template<bool FP16IN>
__global__ void __launch_bounds__(GTHREADS)
k_gemm(const void* __restrict__ x, const float* __restrict__ W,
       __half* __restrict__ h, int n) {
    extern __shared__ unsigned long long sm[];
    float4*    wsf = (float4*)sm;                          // [4096] = W row-major
    ulonglong2* ws = (ulonglong2*)sm;                      // alias: ws[k*32+l]
    unsigned long long* xs = sm + 8192;                    // xs[row*128 + k] = dup(x)
    int tid = threadIdx.x;
    int base = blockIdx.x * GROWS;

    // stage W
    const float4* W4 = (const float4*)W;
    #pragma unroll
    for (int i = tid; i < 4096; i += GTHREADS) wsf[i] = W4[i];

    // stage x rows, duplicated per element
    #pragma unroll
    for (int i = tid; i < GROWS * 32; i += GTHREADS) {
        int r = i >> 5, c = i & 31;
        int rg = base + r; if (rg >= n) rg = n - 1;
        float4 v;
        if (FP16IN) {
            uint2 raw = ((const uint2*)x)[rg * 32 + c];
            __half2 h0 = *(__half2*)&raw.x;
            __half2 h1 = *(__half2*)&raw.y;
            float2 f0 = __half22float2(h0), f1 = __half22float2(h1);
            v = make_float4(f0.x, f0.y, f1.x, f1.y);
        } else {
            v = ((const float4*)x)[rg * 32 + c];
        }
        ulonglong2* dst = (ulonglong2*)(xs + r * 128) + 2 * c;
        ulonglong2 a; a.x = dup32(v.x); a.y = dup32(v.y);
        ulonglong2 b; b.x = dup32(v.z); b.y = dup32(v.w);
        dst[0] = a; dst[1] = b;
    }
    __syncthreads();

    int warp = tid >> 5, lane = tid & 31;
    int rbase = warp * 8;

    unsigned long long acc01[8], acc23[8];
    #pragma unroll
    for (int r = 0; r < 8; r++) { acc01[r] = 0ull; acc23[r] = 0ull; }

    #pragma unroll 2
    for (int k4 = 0; k4 < 32; k4++) {
        ulonglong2 w0 = ws[(k4 * 4 + 0) * 32 + lane];
        ulonglong2 w1 = ws[(k4 * 4 + 1) * 32 + lane];
        ulonglong2 w2 = ws[(k4 * 4 + 2) * 32 + lane];
        ulonglong2 w3 = ws[(k4 * 4 + 3) * 32 + lane];
        #pragma unroll
        for (int r = 0; r < 8; r++) {
            const ulonglong2* xp = (const ulonglong2*)(xs + (rbase + r) * 128) + 2 * k4;
            ulonglong2 xa = xp[0];
            ulonglong2 xb = xp[1];
            FMA2(acc01[r], w0.x, xa.x, acc01[r]);
            FMA2(acc23[r], w0.y, xa.x, acc23[r]);
            FMA2(acc01[r], w1.x, xa.y, acc01[r]);
            FMA2(acc23[r], w1.y, xa.y, acc23[r]);
            FMA2(acc01[r], w2.x, xb.x, acc01[r]);
            FMA2(acc23[r], w2.y, xb.x, acc23[r]);
            FMA2(acc01[r], w3.x, xb.y, acc01[r]);
            FMA2(acc23[r], w3.y, xb.y, acc23[r]);
        }
    }

    #pragma unroll
    for (int r = 0; r < 8; r++) {
        int rg = base + rbase + r;
        if (rg < n) {
            unsigned int a0, a1, a2, a3;
            UNPACK2(a0, a1, acc01[r]);
            UNPACK2(a2, a3, acc23[r]);
            __half2 hx = __floats2half2_rn(__uint_as_float(a0), __uint_as_float(a1));
            __half2 hy = __floats2half2_rn(__uint_as_float(a2), __uint_as_float(a3));
            uint2 o;
            o.x = *(unsigned int*)&hx;
            o.y = *(unsigned int*)&hy;
            ((uint2*)h)[rg * 32 + lane] = o;
        }
    }
}

// ---------------------------------------------------- fused CSR gather
__device__ __forceinline__ float4 h4_load(const uint2* __restrict__ h2, int idx) {
    uint2 raw = __ldg(h2 + idx);
    __half2 a = *(__half2*)&raw.x;
    __half2 b = *(__half2*)&raw.y;
    float2 fa = __half22float2(a), fb = __half22float2(b);
    return make_float4(fa.x, fa.y, fb.x, fb.y);
}

// warp per dst node: r = dinv[d]*( dinv[d]*h[d] + sum_in dinv[s]*h[s] ) + bias
// mode 0: dst(fp16)[d] = r
// mode 1: dst(fp32)[d] = r + emb32 + a16 + b16   (out = emb + l1 + l2 + r)
__global__ void __launch_bounds__(256)
k_gather(const int* __restrict__ off, const int2* __restrict__ edge,
         const float* __restrict__ dinv, const __half* __restrict__ h,
         const float* __restrict__ bias, void* __restrict__ dst,
         const float4* __restrict__ emb32, const uint2* __restrict__ a16,
         const uint2* __restrict__ b16, int n, int mode) {
    int w = (blockIdx.x * 256 + threadIdx.x) >> 5;
    if (w >= n) return;
    int lane = threadIdx.x & 31;
    const uint2* h2 = (const uint2*)h;

    float di = dinv[w];
    float4 hv = h4_load(h2, w * 32 + lane);
    float4 acc  = make_float4(hv.x * di, hv.y * di, hv.z * di, hv.w * di);
    float4 acc2 = make_float4(0.f, 0.f, 0.f, 0.f);

    int beg = off[w], end = off[w + 1];
    int e = beg;
    for (; e + 3 < end; e += 4) {
        int2 e0 = __ldg(edge + e);
        int2 e1 = __ldg(edge + e + 1);
        int2 e2 = __ldg(edge + e + 2);
        int2 e3 = __ldg(edge + e + 3);
        float s0 = __int_as_float(e0.y), s1 = __int_as_float(e1.y);
        float s2 = __int_as_float(e2.y), s3 = __int_as_float(e3.y);
        float4 v0 = h4_load(h2, e0.x * 32 + lane);
        float4 v1 = h4_load(h2, e1.x * 32 + lane);
        float4 v2 = h4_load(h2, e2.x * 32 + lane);
        float4 v3 = h4_load(h2, e3.x * 32 + lane);
        acc.x  += v0.x * s0 + v1.x * s1;
        acc.y  += v0.y * s0 + v1.y * s1;
        acc.z  += v0.z * s0 + v1.z * s1;
        acc.w  += v0.w * s0 + v1.w * s1;
        acc2.x += v2.x * s2 + v3.x * s3;
        acc2.y += v2.y * s2 + v3.y * s3;
        acc2.z += v2.z * s2 + v3.z * s3;
        acc2.w += v2.w * s2 + v3.w * s3;
    }
    for (; e < end; e++) {
        int2 e0 = __ldg(edge + e);
        float s0 = __int_as_float(e0.y);
        float4 v0 = h4_load(h2, e0.x * 32 + lane);
        acc.x += v0.x * s0; acc.y += v0.y * s0;
        acc.z += v0.z * s0; acc.w += v0.w * s0;
    }
    acc.x += acc2.x; acc.y += acc2.y; acc.z += acc2.z; acc.w += acc2.w;

    float4 bv = ((const float4*)bias)[lane];
    float4 r;
    r.x = acc.x * di + bv.x;
    r.y = acc.y * di + bv.y;
    r.z = acc.z * di + bv.z;
    r.w = acc.w * di + bv.w;

    int idx = w * 32 + lane;
    if (mode == 0) {
        __half2 p0 = __floats2half2_rn(r.x, r.y);
        __half2 p1 = __floats2half2_rn(r.z, r.w);
        uint2 o;
        o.x = *(uint32_t*)&p0;
        o.y = *(uint32_t*)&p1;
        ((uint2*)dst)[idx] = o;
    } else {
        float4 em = emb32[idx];
        float4 av = h4_load(a16, idx);
        float4 bv2 = h4_load(b16, idx);
        r.x += em.x + av.x + bv2.x;
        r.y += em.y + av.y + bv2.y;
        r.z += em.z + av.z + bv2.z;
        r.w += em.w + av.w + bv2.w;
        ((float4*)dst)[idx] = r;
    }
}

// ================================================================ launch
extern "C" void kernel_launch(void* const* d_in, const int* in_sizes, int n_in,
                              void* d_out, int out_size) {
    const int*   edge_in = (const int*)d_in[0];   // [2, NE]
    const float* emb     = (const float*)d_in[1]; // [100001, 128]
    const float* W       = (const float*)d_in[2]; // [3,128,128]
    const float* b       = (const float*)d_in[3]; // [3,128]
    float* out = (float*)d_out;                   // [NN,128]

    const int* row = edge_in;
    const int* col = edge_in + NE;

    float* dinv; int *cnt, *off, *cur, *bsum; int2* edg;
    __half *h, *bufA, *bufB;
    cudaGetSymbolAddress((void**)&dinv, g_dinv);
    cudaGetSymbolAddress((void**)&cnt,  g_cnt);
    cudaGetSymbolAddress((void**)&off,  g_off);
    cudaGetSymbolAddress((void**)&cur,  g_cur);
    cudaGetSymbolAddress((void**)&bsum, g_bsum);
    cudaGetSymbolAddress((void**)&edg,  g_edge);
    cudaGetSymbolAddress((void**)&h,    g_h);
    cudaGetSymbolAddress((void**)&bufA, g_bufA);
    cudaGetSymbolAddress((void**)&bufB, g_bufB);

    const int SMEM_G = 65536 + GROWS * 128 * 8;   // W + dup'd x tile = 163840
    cudaFuncSetAttribute(k_gemm<false>, cudaFuncAttributeMaxDynamicSharedMemorySize, SMEM_G);
    cudaFuncSetAttribute(k_gemm<true>,  cudaFuncAttributeMaxDynamicSharedMemorySize, SMEM_G);

    const int gN  = (NN + 255) / 256;
    const int gE  = (NE + 255) / 256;
    const int gG  = (NN + GROWS - 1) / GROWS;
    const int gW  = (NN * 32 + 255) / 256;        // warp per node

    // ---- CSR build ----
    k_zero   <<<gN, 256>>>(cnt, NN);
    k_cnt    <<<gE, 256>>>(col, cnt, NE);
    k_scan1  <<<NB_SCAN, 1024>>>(cnt, off, bsum, NN);
    k_scan3  <<<gN, 256>>>(off, bsum, cur, cnt, dinv, NN);
    k_fillcsr<<<gE, 256>>>(row, col, dinv, cur, edg, NE);

    // layer 0: emb(f32) -> h -> bufA(f16)
    k_gemm<false><<<gG, GTHREADS, SMEM_G>>>(emb, W + 0 * EMB * EMB, h, NN);
    k_gather<<<gW, 256>>>(off, edg, dinv, h, b + 0 * EMB, bufA,
                          (const float4*)emb, (const uint2*)bufA, (const uint2*)bufB, NN, 0);
    // layer 1: bufA(f16) -> h -> bufB(f16)
    k_gemm<true><<<gG, GTHREADS, SMEM_G>>>(bufA, W + 1 * EMB * EMB, h, NN);
    k_gather<<<gW, 256>>>(off, edg, dinv, h, b + 1 * EMB, bufB,
                          (const float4*)emb, (const uint2*)bufA, (const uint2*)bufB, NN, 0);
    // layer 2: bufB(f16) -> h -> out(f32) = r + emb + bufA + bufB
    k_gemm<true><<<gG, GTHREADS, SMEM_G>>>(bufB, W + 2 * EMB * EMB, h, NN);
    k_gather<<<gW, 256>>>(off, edg, dinv, h, b + 2 * EMB, out,
                          (const float4*)emb, (const uint2*)bufA, (const uint2*)bufB, NN, 1);
}